// round 6
// baseline (speedup 1.0000x reference)
#include <cuda_runtime.h>
#include <cuda_bf16.h>
#include <mma.h>
#include <math.h>

using namespace nvcuda;

// Problem shape (fixed): T=256, B=64, D=H=1024
#define TT 256
#define BB 64
#define HH 1024
#define NG 4096      // 4*H
#define TBm 16384    // T*B
#define PKCTA 128    // persistent CTAs (1 per SM, all co-resident)
#define NFL ((TT + 1) * 16)

// ---------------- scratch (device globals: allocation-free rule) -------------
__device__ float g_zx[(size_t)TBm * NG];       // 256 MB: x-projection (gemm out)
__device__ float g_zxp[(size_t)TBm * NG];      // 256 MB: repacked zx (+bias)
__device__ float g_hall[(size_t)TBm * HH];     // 64 MB: layer-0 fp32 h (unused sink)
__device__ __nv_bfloat16 g_hseqh[(size_t)(TT + 1) * BB * HH];  // 33.7 MB h hi seq
__device__ __nv_bfloat16 g_hseql[(size_t)(TT + 1) * BB * HH];  // 33.7 MB h lo seq
__device__ __nv_bfloat16 g_xh[(size_t)TBm * HH];    // 32 MB x hi plane
__device__ __nv_bfloat16 g_xl[(size_t)TBm * HH];    // 32 MB x lo plane
__device__ __nv_bfloat16 g_wxh[(size_t)HH * NG];    // 8 MB input-W hi
__device__ __nv_bfloat16 g_wxl[(size_t)HH * NG];    // 8 MB input-W lo
__device__ __nv_bfloat16 g_wph[(size_t)HH * NG];    // 8 MB packed recurrent W hi
__device__ __nv_bfloat16 g_wpl[(size_t)HH * NG];    // 8 MB packed recurrent W lo
__device__ __align__(16) int g_bar[2 * NFL];        // per-(step,group) flags

// ---------------- helpers ----------------------------------------------------
__device__ __forceinline__ void split_bf16(float x, __nv_bfloat16& hi, __nv_bfloat16& lo) {
    hi = __float2bfloat16(x);
    lo = __float2bfloat16(x - __bfloat162float(hi));
}
__device__ __forceinline__ float sigmoidf_(float x) { return 1.0f / (1.0f + expf(-x)); }

__device__ __forceinline__ void cpa16(void* dst, const void* src) {
    unsigned d = (unsigned)__cvta_generic_to_shared(dst);
    asm volatile("cp.async.cg.shared.global [%0], [%1], 16;" :: "r"(d), "l"(src));
}
__device__ __forceinline__ int ldrelax(const int* p) {
    int v;
    asm volatile("ld.relaxed.gpu.global.b32 %0, [%1];" : "=r"(v) : "l"(p));
    return v;
}

__global__ void init_state_kernel(__nv_bfloat16* hh, __nv_bfloat16* hl, int* bar) {
    int i = blockIdx.x * blockDim.x + threadIdx.x;
    if (i < BB * HH) {                        // zero h(0) = slot 0
        hh[i] = __float2bfloat16(0.0f);
        hl[i] = __float2bfloat16(0.0f);
    }
    if (i < NFL) bar[i] = (i < 16) ? 8 : 0;   // h(0) immediately available
}

// fp32 -> bf16 hi/lo planes (elementwise)
__global__ void split_plane_kernel(const float* __restrict__ a,
                                   __nv_bfloat16* __restrict__ hi,
                                   __nv_bfloat16* __restrict__ lo, size_t n) {
    for (size_t i = (size_t)blockIdx.x * blockDim.x + threadIdx.x; i < n;
         i += (size_t)gridDim.x * blockDim.x) {
        __nv_bfloat16 h, l;
        split_bf16(a[i], h, l);
        hi[i] = h;
        lo[i] = l;
    }
}

// input half of W (rows 0..1023) -> row-major bf16 planes [1024][4096]
__global__ void prep_wx_kernel(const float* __restrict__ W,
                               __nv_bfloat16* __restrict__ hi,
                               __nv_bfloat16* __restrict__ lo) {
    for (size_t o = (size_t)blockIdx.x * blockDim.x + threadIdx.x;
         o < (size_t)HH * NG; o += (size_t)gridDim.x * blockDim.x) {
        __nv_bfloat16 h, l;
        split_bf16(W[o], h, l);
        hi[o] = h;
        lo[o] = l;
    }
}

// recurrent half of W -> per-CTA contiguous slices:
// wp[(c*1024 + k)*32 + g*8 + j] = W[1024+k][g*1024 + c*8 + j]  (hi/lo planes)
__global__ void prep_w_kernel(const float* __restrict__ W,
                              __nv_bfloat16* __restrict__ hi,
                              __nv_bfloat16* __restrict__ lo) {
    for (size_t o = (size_t)blockIdx.x * blockDim.x + threadIdx.x;
         o < (size_t)HH * NG; o += (size_t)gridDim.x * blockDim.x) {
        int col = (int)(o & 31);
        int k   = (int)((o >> 5) & 1023);
        int c   = (int)(o >> 15);
        int g = col >> 3, j = col & 7;
        float v = W[(size_t)(HH + k) * NG + g * HH + c * 8 + j];
        __nv_bfloat16 vh, vl;
        split_bf16(v, vh, vl);
        hi[o] = vh;
        lo[o] = vl;
    }
}

// Repack zx (+bias) into per-(t, CTA) contiguous 8KB blocks
__global__ void repack_zx_kernel(const float* __restrict__ zx,
                                 const float* __restrict__ bias,
                                 float* __restrict__ zxp) {
    for (size_t o = (size_t)blockIdx.x * blockDim.x + threadIdx.x;
         o < (size_t)TBm * NG; o += (size_t)gridDim.x * blockDim.x) {
        int col = (int)(o & 31);
        int row = (int)((o >> 5) & 63);
        int c   = (int)((o >> 11) & 127);
        int t   = (int)(o >> 18);
        int g = col >> 3, j = col & 7;
        int n = g * HH + c * 8 + j;
        zxp[o] = zx[((size_t)t * BB + row) * NG + n] + bias[n];
    }
}

// ---------------- big input-projection GEMM (bf16 planes, 3-stage pipe) ------
#define XBM 128
#define XBN 128
#define XBK 32
#define XST 3

struct GSmem {
    __nv_bfloat16 Ah[XST][XBM][XBK + 8];
    __nv_bfloat16 Al[XST][XBM][XBK + 8];
    __nv_bfloat16 Bh[XST][XBK][XBN + 8];
    __nv_bfloat16 Bl[XST][XBK][XBN + 8];
};

__global__ __launch_bounds__(256) void gemm_x_bf16(
    const __nv_bfloat16* __restrict__ Aph, const __nv_bfloat16* __restrict__ Apl,
    const __nv_bfloat16* __restrict__ Bph, const __nv_bfloat16* __restrict__ Bpl,
    float* __restrict__ Z)
{
    extern __shared__ unsigned char sraw[];
    GSmem* S = (GSmem*)sraw;

    const int bm = blockIdx.y * XBM;
    const int bn = blockIdx.x * XBN;
    const int tid = threadIdx.x;
    const int warp = tid >> 5;
    const int wm = (warp >> 2) * 64;
    const int wn = (warp & 3) * 32;

    auto load_stage = [&](int s, int kb) {
#pragma unroll
        for (int p = 0; p < 2; ++p) {         // A planes: 128 x 32 = 512 x 16B each
            int i = tid + p * 256;
            int r = i >> 2, off = (i & 3) * 8;
            cpa16(&S->Ah[s][r][off], Aph + (size_t)(bm + r) * HH + kb + off);
            cpa16(&S->Al[s][r][off], Apl + (size_t)(bm + r) * HH + kb + off);
        }
#pragma unroll
        for (int p = 0; p < 2; ++p) {         // B planes: 32 x 128 = 512 x 16B each
            int i = tid + p * 256;
            int r = i >> 4, off = (i & 15) * 8;
            cpa16(&S->Bh[s][r][off], Bph + (size_t)(kb + r) * NG + bn + off);
            cpa16(&S->Bl[s][r][off], Bpl + (size_t)(kb + r) * NG + bn + off);
        }
    };

    load_stage(0, 0);
    asm volatile("cp.async.commit_group;" ::: "memory");
    load_stage(1, XBK);
    asm volatile("cp.async.commit_group;" ::: "memory");

    wmma::fragment<wmma::accumulator, 16, 16, 16, float> acc[4][2];
#pragma unroll
    for (int i = 0; i < 4; ++i)
#pragma unroll
        for (int j = 0; j < 2; ++j)
            wmma::fill_fragment(acc[i][j], 0.0f);

    const int NKT = HH / XBK;   // 32
    for (int kt = 0; kt < NKT; ++kt) {
        asm volatile("cp.async.wait_group 1;" ::: "memory");
        __syncthreads();
        int s = kt % XST;

#pragma unroll
        for (int kk = 0; kk < XBK; kk += 16) {
            wmma::fragment<wmma::matrix_a, 16, 16, 16, __nv_bfloat16, wmma::row_major> ah[4], al[4];
            wmma::fragment<wmma::matrix_b, 16, 16, 16, __nv_bfloat16, wmma::row_major> bh[2], bl[2];
#pragma unroll
            for (int i = 0; i < 4; ++i) {
                wmma::load_matrix_sync(ah[i], &S->Ah[s][wm + 16 * i][kk], XBK + 8);
                wmma::load_matrix_sync(al[i], &S->Al[s][wm + 16 * i][kk], XBK + 8);
            }
#pragma unroll
            for (int j = 0; j < 2; ++j) {
                wmma::load_matrix_sync(bh[j], &S->Bh[s][kk][wn + 16 * j], XBN + 8);
                wmma::load_matrix_sync(bl[j], &S->Bl[s][kk][wn + 16 * j], XBN + 8);
            }
#pragma unroll
            for (int i = 0; i < 4; ++i)
#pragma unroll
                for (int j = 0; j < 2; ++j) {
                    wmma::mma_sync(acc[i][j], ah[i], bh[j], acc[i][j]);
                    wmma::mma_sync(acc[i][j], ah[i], bl[j], acc[i][j]);
                    wmma::mma_sync(acc[i][j], al[i], bh[j], acc[i][j]);
                }
        }

        if (kt + 2 < NKT) load_stage((kt + 2) % XST, (kt + 2) * XBK);
        asm volatile("cp.async.commit_group;" ::: "memory");
    }

#pragma unroll
    for (int i = 0; i < 4; ++i)
#pragma unroll
        for (int j = 0; j < 2; ++j)
            wmma::store_matrix_sync(Z + (size_t)(bm + wm + 16 * i) * NG + bn + wn + 16 * j,
                                    acc[i][j], NG, wmma::mem_row_major);
}

// ---------------- persistent recurrent kernel ---------------------------------
// 128 CTAs x 256 threads. CTA c owns hidden cols [c*8, c*8+8). Global barrier
// replaced by 16 per-(step,chunk-group) flags: chunk g of h(t) (k in [64g,64g+64))
// is produced by CTAs 8g..8g+7; consumers poll flag (t,g) before loading chunk g.
// h stored as full sequence (slot t = h(t)) -> no WAR hazards.
#define CH 64        // k per chunk
#define NCH 16       // chunks per step
#define HST 72       // h smem stride (64+8)
#define WST 32       // W smem stride

struct PSmem {
    __nv_bfloat16 wh[HH][WST];        // 64 KB
    __nv_bfloat16 wl[HH][WST];        // 64 KB
    __nv_bfloat16 hh[3][BB][HST];     // 27 KB
    __nv_bfloat16 hl[3][BB][HST];     // 27 KB
    float zxs[BB][32];                // 8 KB
    float cs[BB][8];                  // 2 KB
    float zs[2][BB][32];              // 16 KB
};                                    // 208 KB

__global__ __launch_bounds__(256) void lstm_persist_kernel(
    const float* __restrict__ zxp,           // [256][128][64][32] packed (+bias)
    const __nv_bfloat16* __restrict__ wph,
    const __nv_bfloat16* __restrict__ wpl,
    __nv_bfloat16* __restrict__ hseqh,       // [257][64*1024]
    __nv_bfloat16* __restrict__ hseql,
    float* __restrict__ hout_all,            // [256][64][1024] fp32
    int* __restrict__ barL)                  // [(TT+1)*16]
{
    extern __shared__ unsigned char smem_raw[];
    PSmem* S = (PSmem*)smem_raw;

    const int tid  = threadIdx.x;
    const int warp = tid >> 5;
    const int cblk = blockIdx.x;             // 0..127
    const int mt   = warp & 3;               // m-tile (16 rows)
    const int kh   = warp >> 2;              // k-half (0/1)
    const int mygrp = cblk >> 3;

    // ---- load W slice into SMEM once ----
    for (int i = tid; i < HH * 4; i += 256) {
        int row = i >> 2, off = (i & 3) * 8;
        cpa16(&S->wh[row][off], wph + ((size_t)cblk * HH + row) * 32 + off);
        cpa16(&S->wl[row][off], wpl + ((size_t)cblk * HH + row) * 32 + off);
    }
    asm volatile("cp.async.commit_group;\ncp.async.wait_group 0;" ::: "memory");
    for (int e = tid; e < BB * 8; e += 256) ((float*)S->cs)[e] = 0.0f;
    __syncthreads();

    for (int t = 0; t < TT; ++t) {
        const __nv_bfloat16* hin_h = hseqh + (size_t)t * BB * HH;
        const __nv_bfloat16* hin_l = hseql + (size_t)t * BB * HH;
        __nv_bfloat16* hout_h = hseqh + (size_t)(t + 1) * BB * HH;
        __nv_bfloat16* hout_l = hseql + (size_t)(t + 1) * BB * HH;
        const int* fl = barL + t * 16;

        unsigned mask = 0;
        auto ensure = [&](int g) {
            if ((mask >> g) & 1u) return;
            const int* p = fl + (g & ~3);
            for (;;) {
                unsigned m = 0;
                if (ldrelax(p + 0) >= 8) m |= 1u;
                if (ldrelax(p + 1) >= 8) m |= 2u;
                if (ldrelax(p + 2) >= 8) m |= 4u;
                if (ldrelax(p + 3) >= 8) m |= 8u;
                if ((m >> (g & 3)) & 1u) { mask |= m << (g & ~3); break; }
                __nanosleep(32);
            }
            asm volatile("fence.acq_rel.gpu;" ::: "memory");
        };

        auto load_chunk = [&](int slot, int ic) {
#pragma unroll
            for (int p = 0; p < 2; ++p) {
                int i = tid + p * 256;
                int r = i >> 3, off = (i & 7) * 8;
                cpa16(&S->hh[slot][r][off], hin_h + (size_t)r * HH + ic * CH + off);
                cpa16(&S->hl[slot][r][off], hin_l + (size_t)r * HH + ic * CH + off);
            }
        };

        // prefetch zx block + chunk0; then chunk1
        {
            const float* zsrc = zxp + ((size_t)t * PKCTA + cblk) * (BB * 32);
#pragma unroll
            for (int p = 0; p < 2; ++p) {
                int i = tid + p * 256;
                cpa16(((char*)S->zxs) + i * 16, ((const char*)zsrc) + i * 16);
            }
            ensure(0);
            load_chunk(0, 0);
            asm volatile("cp.async.commit_group;" ::: "memory");
            ensure(1);
            load_chunk(1, 1);
            asm volatile("cp.async.commit_group;" ::: "memory");
        }

        wmma::fragment<wmma::accumulator, 16, 16, 16, float> acc[2][3];
#pragma unroll
        for (int nt = 0; nt < 2; ++nt)
#pragma unroll
            for (int p = 0; p < 3; ++p)
                wmma::fill_fragment(acc[nt][p], 0.0f);

        for (int ic = 0; ic < NCH; ++ic) {
            asm volatile("cp.async.wait_group 1;" ::: "memory");
            __syncthreads();
            int sl = ic % 3;

#pragma unroll
            for (int kk = 0; kk < 2; ++kk) {
                int kb = kh * 32 + kk * 16;
                wmma::fragment<wmma::matrix_a, 16, 16, 16, __nv_bfloat16, wmma::row_major> ah, al;
                wmma::load_matrix_sync(ah, &S->hh[sl][mt * 16][kb], HST);
                wmma::load_matrix_sync(al, &S->hl[sl][mt * 16][kb], HST);
                int krow = ic * CH + kb;
#pragma unroll
                for (int nt = 0; nt < 2; ++nt) {
                    wmma::fragment<wmma::matrix_b, 16, 16, 16, __nv_bfloat16, wmma::row_major> bh, bl;
                    wmma::load_matrix_sync(bh, &S->wh[krow][nt * 16], WST);
                    wmma::load_matrix_sync(bl, &S->wl[krow][nt * 16], WST);
                    wmma::mma_sync(acc[nt][0], ah, bh, acc[nt][0]);
                    wmma::mma_sync(acc[nt][1], ah, bl, acc[nt][1]);
                    wmma::mma_sync(acc[nt][2], al, bh, acc[nt][2]);
                }
            }

            if (ic + 2 < NCH) {
                ensure(ic + 2);
                load_chunk((ic + 2) % 3, ic + 2);
            }
            asm volatile("cp.async.commit_group;" ::: "memory");
        }
        asm volatile("cp.async.wait_group 0;" ::: "memory");

        // ---- sum 3 passes, park partials ----
#pragma unroll
        for (int nt = 0; nt < 2; ++nt) {
#pragma unroll
            for (int e = 0; e < acc[nt][0].num_elements; ++e)
                acc[nt][0].x[e] += acc[nt][1].x[e] + acc[nt][2].x[e];
            wmma::store_matrix_sync(&S->zs[kh][mt * 16][nt * 16], acc[nt][0], 32,
                                    wmma::mem_row_major);
        }
        __syncthreads();

        // ---- gate fusion ----
#pragma unroll
        for (int e = tid; e < BB * 8; e += 256) {
            int row = e & 63, j = e >> 6;
            float zi = S->zs[0][row][j]      + S->zs[1][row][j]      + S->zxs[row][j];
            float zj = S->zs[0][row][8 + j]  + S->zs[1][row][8 + j]  + S->zxs[row][8 + j];
            float zf = S->zs[0][row][16 + j] + S->zs[1][row][16 + j] + S->zxs[row][16 + j];
            float zo = S->zs[0][row][24 + j] + S->zs[1][row][24 + j] + S->zxs[row][24 + j];
            float cold = S->cs[row][j];
            float nc = cold * sigmoidf_(zf + 1.0f) + sigmoidf_(zi) * tanhf(zj);
            float nh = tanhf(nc) * sigmoidf_(zo);
            S->cs[row][j] = nc;
            size_t o = (size_t)row * HH + cblk * 8 + j;
            __nv_bfloat16 hi, lo;
            split_bf16(nh, hi, lo);
            hout_h[o] = hi;
            hout_l[o] = lo;
            hout_all[(size_t)t * BB * HH + o] = nh;
        }
        __syncthreads();

        // ---- signal: this CTA's slice of h(t+1) is ready ----
        if (tid == 0) {
            __threadfence();
            atomicAdd(barL + (t + 1) * 16 + mygrp, 1);
        }
        // no global barrier: consumers gate on flags per chunk
    }
}

// ---------------- launch ------------------------------------------------------
extern "C" void kernel_launch(void* const* d_in, const int* in_sizes, int n_in,
                              void* d_out, int out_size)
{
    const float* x  = (const float*)d_in[0];
    const float* W0 = (const float*)d_in[1];
    const float* b0 = (const float*)d_in[2];
    const float* W1 = (const float*)d_in[3];
    const float* b1 = (const float*)d_in[4];
    float* out = (float*)d_out;

    float *zx, *zxp, *hall;
    __nv_bfloat16 *hseqh, *hseql, *xh, *xl, *wxh, *wxl, *wph, *wpl;
    int* bar;
    cudaGetSymbolAddress((void**)&zx,    g_zx);
    cudaGetSymbolAddress((void**)&zxp,   g_zxp);
    cudaGetSymbolAddress((void**)&hall,  g_hall);
    cudaGetSymbolAddress((void**)&hseqh, g_hseqh);
    cudaGetSymbolAddress((void**)&hseql, g_hseql);
    cudaGetSymbolAddress((void**)&xh,    g_xh);
    cudaGetSymbolAddress((void**)&xl,    g_xl);
    cudaGetSymbolAddress((void**)&wxh,   g_wxh);
    cudaGetSymbolAddress((void**)&wxl,   g_wxl);
    cudaGetSymbolAddress((void**)&wph,   g_wph);
    cudaGetSymbolAddress((void**)&wpl,   g_wpl);
    cudaGetSymbolAddress((void**)&bar,   g_bar);

    const int psmem = (int)sizeof(PSmem);
    cudaFuncSetAttribute(lstm_persist_kernel,
                         cudaFuncAttributeMaxDynamicSharedMemorySize, psmem);
    const int gsmem = (int)sizeof(GSmem);
    cudaFuncSetAttribute(gemm_x_bf16,
                         cudaFuncAttributeMaxDynamicSharedMemorySize, gsmem);

    const dim3 ggrid(NG / XBN, TBm / XBM);   // (32, 128)

    // ---- layer 0 ----
    split_plane_kernel<<<2048, 256>>>(x, xh, xl, (size_t)TBm * HH);
    prep_wx_kernel<<<2048, 256>>>(W0, wxh, wxl);
    prep_w_kernel<<<2048, 256>>>(W0, wph, wpl);
    init_state_kernel<<<(BB * HH + 255) / 256, 256>>>(hseqh, hseql, bar);
    gemm_x_bf16<<<ggrid, 256, gsmem>>>(xh, xl, wxh, wxl, zx);
    repack_zx_kernel<<<8192, 256>>>(zx, b0, zxp);
    lstm_persist_kernel<<<PKCTA, 256, psmem>>>(zxp, wph, wpl, hseqh, hseql, hall, bar);

    // ---- layer 1 (gemm A = h sequence planes, slots 1..256) ----
    prep_wx_kernel<<<2048, 256>>>(W1, wxh, wxl);
    prep_w_kernel<<<2048, 256>>>(W1, wph, wpl);
    init_state_kernel<<<(BB * HH + 255) / 256, 256>>>(hseqh, hseql, bar + NFL);
    gemm_x_bf16<<<ggrid, 256, gsmem>>>(hseqh + (size_t)BB * HH, hseql + (size_t)BB * HH,
                                       wxh, wxl, zx);
    repack_zx_kernel<<<8192, 256>>>(zx, b1, zxp);
    lstm_persist_kernel<<<PKCTA, 256, psmem>>>(zxp, wph, wpl, hseqh, hseql, out, bar + NFL);
}

// round 7
// speedup vs baseline: 1.3488x; 1.3488x over previous
#include <cuda_runtime.h>
#include <cuda_bf16.h>
#include <mma.h>
#include <math.h>

using namespace nvcuda;

// Problem shape (fixed): T=256, B=64, D=H=1024
#define TT 256
#define BB 64
#define HH 1024
#define NG 4096      // 4*H
#define TBm 16384    // T*B
#define PKCTA 128    // persistent CTAs (1 per SM, all co-resident)

// ---------------- scratch (device globals: allocation-free rule) -------------
__device__ float g_zx[(size_t)TBm * NG];       // 256 MB: x-projection (gemm out)
__device__ float g_zxp[(size_t)TBm * NG];      // 256 MB: repacked zx (+bias)
__device__ float g_hall[(size_t)TBm * HH];     // 64 MB: layer-0 fp32 h sink
__device__ __nv_bfloat16 g_hseqh[(size_t)(TT + 1) * BB * HH];  // h hi sequence
__device__ __nv_bfloat16 g_hseql[(size_t)(TT + 1) * BB * HH];  // h lo sequence
__device__ __nv_bfloat16 g_xh[(size_t)TBm * HH];    // x hi plane
__device__ __nv_bfloat16 g_xl[(size_t)TBm * HH];    // x lo plane
__device__ __nv_bfloat16 g_wxh[(size_t)HH * NG];    // input-W hi
__device__ __nv_bfloat16 g_wxl[(size_t)HH * NG];    // input-W lo
__device__ __nv_bfloat16 g_wph[(size_t)HH * NG];    // packed recurrent W hi
__device__ __nv_bfloat16 g_wpl[(size_t)HH * NG];    // packed recurrent W lo
__device__ __align__(16) int g_bar[2 * TT];         // per-step barrier counters

// ---------------- helpers ----------------------------------------------------
__device__ __forceinline__ void split_bf16(float x, __nv_bfloat16& hi, __nv_bfloat16& lo) {
    hi = __float2bfloat16(x);
    lo = __float2bfloat16(x - __bfloat162float(hi));
}
__device__ __forceinline__ float sigmoidf_(float x) { return 1.0f / (1.0f + expf(-x)); }

__device__ __forceinline__ void cpa16(void* dst, const void* src) {
    unsigned d = (unsigned)__cvta_generic_to_shared(dst);
    asm volatile("cp.async.cg.shared.global [%0], [%1], 16;" :: "r"(d), "l"(src));
}

__global__ void init_state_kernel(__nv_bfloat16* hh, __nv_bfloat16* hl, int* bar) {
    int i = blockIdx.x * blockDim.x + threadIdx.x;
    if (i < BB * HH) {                        // zero h(0) = slot 0
        hh[i] = __float2bfloat16(0.0f);
        hl[i] = __float2bfloat16(0.0f);
    }
    if (i < TT) bar[i] = 0;
}

// fp32 -> bf16 hi/lo planes (elementwise)
__global__ void split_plane_kernel(const float* __restrict__ a,
                                   __nv_bfloat16* __restrict__ hi,
                                   __nv_bfloat16* __restrict__ lo, size_t n) {
    for (size_t i = (size_t)blockIdx.x * blockDim.x + threadIdx.x; i < n;
         i += (size_t)gridDim.x * blockDim.x) {
        __nv_bfloat16 h, l;
        split_bf16(a[i], h, l);
        hi[i] = h;
        lo[i] = l;
    }
}

// input half of W (rows 0..1023) -> row-major bf16 planes [1024][4096]
__global__ void prep_wx_kernel(const float* __restrict__ W,
                               __nv_bfloat16* __restrict__ hi,
                               __nv_bfloat16* __restrict__ lo) {
    for (size_t o = (size_t)blockIdx.x * blockDim.x + threadIdx.x;
         o < (size_t)HH * NG; o += (size_t)gridDim.x * blockDim.x) {
        __nv_bfloat16 h, l;
        split_bf16(W[o], h, l);
        hi[o] = h;
        lo[o] = l;
    }
}

// recurrent half of W -> per-CTA contiguous slices:
// wp[(c*1024 + k)*32 + g*8 + j] = W[1024+k][g*1024 + c*8 + j]  (hi/lo planes)
__global__ void prep_w_kernel(const float* __restrict__ W,
                              __nv_bfloat16* __restrict__ hi,
                              __nv_bfloat16* __restrict__ lo) {
    for (size_t o = (size_t)blockIdx.x * blockDim.x + threadIdx.x;
         o < (size_t)HH * NG; o += (size_t)gridDim.x * blockDim.x) {
        int col = (int)(o & 31);
        int k   = (int)((o >> 5) & 1023);
        int c   = (int)(o >> 15);
        int g = col >> 3, j = col & 7;
        float v = W[(size_t)(HH + k) * NG + g * HH + c * 8 + j];
        __nv_bfloat16 vh, vl;
        split_bf16(v, vh, vl);
        hi[o] = vh;
        lo[o] = vl;
    }
}

// Repack zx (+bias) into per-(t, CTA) contiguous 8KB blocks
__global__ void repack_zx_kernel(const float* __restrict__ zx,
                                 const float* __restrict__ bias,
                                 float* __restrict__ zxp) {
    for (size_t o = (size_t)blockIdx.x * blockDim.x + threadIdx.x;
         o < (size_t)TBm * NG; o += (size_t)gridDim.x * blockDim.x) {
        int col = (int)(o & 31);
        int row = (int)((o >> 5) & 63);
        int c   = (int)((o >> 11) & 127);
        int t   = (int)(o >> 18);
        int g = col >> 3, j = col & 7;
        int n = g * HH + c * 8 + j;
        zxp[o] = zx[((size_t)t * BB + row) * NG + n] + bias[n];
    }
}

// ---------------- big input-projection GEMM (bf16 planes, 3-stage pipe) ------
#define XBM 128
#define XBN 128
#define XBK 32
#define XST 3

struct GSmem {
    __nv_bfloat16 Ah[XST][XBM][XBK + 8];
    __nv_bfloat16 Al[XST][XBM][XBK + 8];
    __nv_bfloat16 Bh[XST][XBK][XBN + 8];
    __nv_bfloat16 Bl[XST][XBK][XBN + 8];
};

__global__ __launch_bounds__(256) void gemm_x_bf16(
    const __nv_bfloat16* __restrict__ Aph, const __nv_bfloat16* __restrict__ Apl,
    const __nv_bfloat16* __restrict__ Bph, const __nv_bfloat16* __restrict__ Bpl,
    float* __restrict__ Z)
{
    extern __shared__ unsigned char sraw[];
    GSmem* S = (GSmem*)sraw;

    const int bm = blockIdx.y * XBM;
    const int bn = blockIdx.x * XBN;
    const int tid = threadIdx.x;
    const int warp = tid >> 5;
    const int wm = (warp >> 2) * 64;
    const int wn = (warp & 3) * 32;

    auto load_stage = [&](int s, int kb) {
#pragma unroll
        for (int p = 0; p < 2; ++p) {
            int i = tid + p * 256;
            int r = i >> 2, off = (i & 3) * 8;
            cpa16(&S->Ah[s][r][off], Aph + (size_t)(bm + r) * HH + kb + off);
            cpa16(&S->Al[s][r][off], Apl + (size_t)(bm + r) * HH + kb + off);
        }
#pragma unroll
        for (int p = 0; p < 2; ++p) {
            int i = tid + p * 256;
            int r = i >> 4, off = (i & 15) * 8;
            cpa16(&S->Bh[s][r][off], Bph + (size_t)(kb + r) * NG + bn + off);
            cpa16(&S->Bl[s][r][off], Bpl + (size_t)(kb + r) * NG + bn + off);
        }
    };

    load_stage(0, 0);
    asm volatile("cp.async.commit_group;" ::: "memory");
    load_stage(1, XBK);
    asm volatile("cp.async.commit_group;" ::: "memory");

    wmma::fragment<wmma::accumulator, 16, 16, 16, float> acc[4][2];
#pragma unroll
    for (int i = 0; i < 4; ++i)
#pragma unroll
        for (int j = 0; j < 2; ++j)
            wmma::fill_fragment(acc[i][j], 0.0f);

    const int NKT = HH / XBK;   // 32
    for (int kt = 0; kt < NKT; ++kt) {
        asm volatile("cp.async.wait_group 1;" ::: "memory");
        __syncthreads();
        int s = kt % XST;

#pragma unroll
        for (int kk = 0; kk < XBK; kk += 16) {
            wmma::fragment<wmma::matrix_a, 16, 16, 16, __nv_bfloat16, wmma::row_major> ah[4], al[4];
            wmma::fragment<wmma::matrix_b, 16, 16, 16, __nv_bfloat16, wmma::row_major> bh[2], bl[2];
#pragma unroll
            for (int i = 0; i < 4; ++i) {
                wmma::load_matrix_sync(ah[i], &S->Ah[s][wm + 16 * i][kk], XBK + 8);
                wmma::load_matrix_sync(al[i], &S->Al[s][wm + 16 * i][kk], XBK + 8);
            }
#pragma unroll
            for (int j = 0; j < 2; ++j) {
                wmma::load_matrix_sync(bh[j], &S->Bh[s][kk][wn + 16 * j], XBN + 8);
                wmma::load_matrix_sync(bl[j], &S->Bl[s][kk][wn + 16 * j], XBN + 8);
            }
#pragma unroll
            for (int i = 0; i < 4; ++i)
#pragma unroll
                for (int j = 0; j < 2; ++j) {
                    wmma::mma_sync(acc[i][j], ah[i], bh[j], acc[i][j]);
                    wmma::mma_sync(acc[i][j], ah[i], bl[j], acc[i][j]);
                    wmma::mma_sync(acc[i][j], al[i], bh[j], acc[i][j]);
                }
        }

        if (kt + 2 < NKT) load_stage((kt + 2) % XST, (kt + 2) * XBK);
        asm volatile("cp.async.commit_group;" ::: "memory");
    }

#pragma unroll
    for (int i = 0; i < 4; ++i)
#pragma unroll
        for (int j = 0; j < 2; ++j)
            wmma::store_matrix_sync(Z + (size_t)(bm + wm + 16 * i) * NG + bn + wn + 16 * j,
                                    acc[i][j], NG, wmma::mem_row_major);
}

// ---------------- persistent recurrent kernel ---------------------------------
// 128 CTAs x 256 threads. CTA c owns hidden cols [c*8, c*8+8). Warp (mt,kh)
// consumes only h rows [mt*16,mt*16+16) x k in [64*ic+32*kh, +32): each warp
// streams its OWN 16x32 subtile through a private 3-slot cp.async ring —
// NO intra-loop __syncthreads, no cross-warp waits. W resident in SMEM.
#define CH 64        // k per chunk
#define NCH 16       // chunks per step
#define HSTW 40      // per-warp h tile stride (32+8): 80B rows, ldsm conflict-free
#define WST 32       // W smem stride

struct PSmem {
    __nv_bfloat16 wh[HH][WST];          // 64 KB
    __nv_bfloat16 wl[HH][WST];          // 64 KB
    __nv_bfloat16 hws[8][3][16][HSTW];  // 30 KB  (hi plane, per-warp slots)
    __nv_bfloat16 lws[8][3][16][HSTW];  // 30 KB  (lo plane)
    float zxs[BB][32];                  // 8 KB
    float cs[BB][8];                    // 2 KB
    float zs[2][BB][32];                // 16 KB
};                                      // 219,136 B = 214 KB

__global__ __launch_bounds__(256) void lstm_persist_kernel(
    const float* __restrict__ zxp,           // [256][128][64][32] packed (+bias)
    const __nv_bfloat16* __restrict__ wph,
    const __nv_bfloat16* __restrict__ wpl,
    __nv_bfloat16* __restrict__ hseqh,       // [257][64*1024]
    __nv_bfloat16* __restrict__ hseql,
    float* __restrict__ hout_all,            // [256][64][1024] fp32
    int* __restrict__ bar)                   // [TT]
{
    extern __shared__ unsigned char smem_raw[];
    PSmem* S = (PSmem*)smem_raw;

    const int tid  = threadIdx.x;
    const int warp = tid >> 5;
    const int lane = tid & 31;
    const int cblk = blockIdx.x;             // 0..127
    const int mt   = warp & 3;               // m-tile (16 rows)
    const int kh   = warp >> 2;              // k-half (0/1)
    const int wrow = mt * 16;

    // ---- load W slice into SMEM once ----
    for (int i = tid; i < HH * 4; i += 256) {
        int row = i >> 2, off = (i & 3) * 8;
        cpa16(&S->wh[row][off], wph + ((size_t)cblk * HH + row) * 32 + off);
        cpa16(&S->wl[row][off], wpl + ((size_t)cblk * HH + row) * 32 + off);
    }
    asm volatile("cp.async.commit_group;\ncp.async.wait_group 0;" ::: "memory");
    for (int e = tid; e < BB * 8; e += 256) ((float*)S->cs)[e] = 0.0f;
    __syncthreads();

    for (int t = 0; t < TT; ++t) {
        const __nv_bfloat16* hin_h = hseqh + (size_t)t * BB * HH;
        const __nv_bfloat16* hin_l = hseql + (size_t)t * BB * HH;
        __nv_bfloat16* hout_h = hseqh + (size_t)(t + 1) * BB * HH;
        __nv_bfloat16* hout_l = hseql + (size_t)(t + 1) * BB * HH;

        // per-warp private chunk loader: 16 rows x 32 k, both planes
        auto wload = [&](int slot, int ic) {
            int kbase = ic * CH + kh * 32;
#pragma unroll
            for (int p = 0; p < 2; ++p) {
                int idx = lane + p * 32;       // 0..63
                int r = idx >> 2, off = (idx & 3) * 8;
                const __nv_bfloat16* sh = hin_h + (size_t)(wrow + r) * HH + kbase + off;
                const __nv_bfloat16* sl = hin_l + (size_t)(wrow + r) * HH + kbase + off;
                cpa16(&S->hws[warp][slot][r][off], sh);
                cpa16(&S->lws[warp][slot][r][off], sl);
            }
        };

        // group 0: zx share (all threads) + own chunk0; then chunks 1,2
        {
            const float* zsrc = zxp + ((size_t)t * PKCTA + cblk) * (BB * 32);
#pragma unroll
            for (int p = 0; p < 2; ++p) {
                int i = tid + p * 256;
                cpa16(((char*)S->zxs) + i * 16, ((const char*)zsrc) + i * 16);
            }
            wload(0, 0);
            asm volatile("cp.async.commit_group;" ::: "memory");
            wload(1, 1);
            asm volatile("cp.async.commit_group;" ::: "memory");
            wload(2, 2);
            asm volatile("cp.async.commit_group;" ::: "memory");
        }

        wmma::fragment<wmma::accumulator, 16, 16, 16, float> acc[2][3];
#pragma unroll
        for (int nt = 0; nt < 2; ++nt)
#pragma unroll
            for (int p = 0; p < 3; ++p)
                wmma::fill_fragment(acc[nt][p], 0.0f);

        // ---- sync-free per-warp chunk loop ----
        for (int ic = 0; ic < NCH; ++ic) {
            asm volatile("cp.async.wait_group 2;" ::: "memory");
            int sl = ic % 3;

#pragma unroll
            for (int kk = 0; kk < 2; ++kk) {
                wmma::fragment<wmma::matrix_a, 16, 16, 16, __nv_bfloat16, wmma::row_major> ah, al;
                wmma::load_matrix_sync(ah, &S->hws[warp][sl][0][kk * 16], HSTW);
                wmma::load_matrix_sync(al, &S->lws[warp][sl][0][kk * 16], HSTW);
                int krow = ic * CH + kh * 32 + kk * 16;
#pragma unroll
                for (int nt = 0; nt < 2; ++nt) {
                    wmma::fragment<wmma::matrix_b, 16, 16, 16, __nv_bfloat16, wmma::row_major> bh, bl;
                    wmma::load_matrix_sync(bh, &S->wh[krow][nt * 16], WST);
                    wmma::load_matrix_sync(bl, &S->wl[krow][nt * 16], WST);
                    wmma::mma_sync(acc[nt][0], ah, bh, acc[nt][0]);
                    wmma::mma_sync(acc[nt][1], ah, bl, acc[nt][1]);
                    wmma::mma_sync(acc[nt][2], al, bh, acc[nt][2]);
                }
            }

            if (ic + 3 < NCH) wload((ic + 3) % 3, ic + 3);
            asm volatile("cp.async.commit_group;" ::: "memory");
        }
        asm volatile("cp.async.wait_group 0;" ::: "memory");

        // ---- sum 3 passes, park partials ----
#pragma unroll
        for (int nt = 0; nt < 2; ++nt) {
#pragma unroll
            for (int e = 0; e < acc[nt][0].num_elements; ++e)
                acc[nt][0].x[e] += acc[nt][1].x[e] + acc[nt][2].x[e];
            wmma::store_matrix_sync(&S->zs[kh][mt * 16][nt * 16], acc[nt][0], 32,
                                    wmma::mem_row_major);
        }
        __syncthreads();

        // ---- gate fusion ----
#pragma unroll
        for (int e = tid; e < BB * 8; e += 256) {
            int row = e & 63, j = e >> 6;
            float zi = S->zs[0][row][j]      + S->zs[1][row][j]      + S->zxs[row][j];
            float zj = S->zs[0][row][8 + j]  + S->zs[1][row][8 + j]  + S->zxs[row][8 + j];
            float zf = S->zs[0][row][16 + j] + S->zs[1][row][16 + j] + S->zxs[row][16 + j];
            float zo = S->zs[0][row][24 + j] + S->zs[1][row][24 + j] + S->zxs[row][24 + j];
            float cold = S->cs[row][j];
            float nc = cold * sigmoidf_(zf + 1.0f) + sigmoidf_(zi) * tanhf(zj);
            float nh = tanhf(nc) * sigmoidf_(zo);
            S->cs[row][j] = nc;
            size_t o = (size_t)row * HH + cblk * 8 + j;
            __nv_bfloat16 hi, lo;
            split_bf16(nh, hi, lo);
            hout_h[o] = hi;
            hout_l[o] = lo;
            hout_all[(size_t)t * BB * HH + o] = nh;
        }
        __syncthreads();

        // ---- per-step grid barrier (release/acquire) ----
        if (tid == 0) {
            __threadfence();
            atomicAdd(&bar[t], 1);
            int v;
            do {
                asm volatile("ld.global.acquire.gpu.b32 %0, [%1];"
                             : "=r"(v) : "l"(bar + t) : "memory");
                if (v < PKCTA) __nanosleep(64);
            } while (v < PKCTA);
        }
        __syncthreads();
    }
}

// ---------------- launch ------------------------------------------------------
extern "C" void kernel_launch(void* const* d_in, const int* in_sizes, int n_in,
                              void* d_out, int out_size)
{
    const float* x  = (const float*)d_in[0];
    const float* W0 = (const float*)d_in[1];
    const float* b0 = (const float*)d_in[2];
    const float* W1 = (const float*)d_in[3];
    const float* b1 = (const float*)d_in[4];
    float* out = (float*)d_out;

    float *zx, *zxp, *hall;
    __nv_bfloat16 *hseqh, *hseql, *xh, *xl, *wxh, *wxl, *wph, *wpl;
    int* bar;
    cudaGetSymbolAddress((void**)&zx,    g_zx);
    cudaGetSymbolAddress((void**)&zxp,   g_zxp);
    cudaGetSymbolAddress((void**)&hall,  g_hall);
    cudaGetSymbolAddress((void**)&hseqh, g_hseqh);
    cudaGetSymbolAddress((void**)&hseql, g_hseql);
    cudaGetSymbolAddress((void**)&xh,    g_xh);
    cudaGetSymbolAddress((void**)&xl,    g_xl);
    cudaGetSymbolAddress((void**)&wxh,   g_wxh);
    cudaGetSymbolAddress((void**)&wxl,   g_wxl);
    cudaGetSymbolAddress((void**)&wph,   g_wph);
    cudaGetSymbolAddress((void**)&wpl,   g_wpl);
    cudaGetSymbolAddress((void**)&bar,   g_bar);

    const int psmem = (int)sizeof(PSmem);
    cudaFuncSetAttribute(lstm_persist_kernel,
                         cudaFuncAttributeMaxDynamicSharedMemorySize, psmem);
    const int gsmem = (int)sizeof(GSmem);
    cudaFuncSetAttribute(gemm_x_bf16,
                         cudaFuncAttributeMaxDynamicSharedMemorySize, gsmem);

    const dim3 ggrid(NG / XBN, TBm / XBM);   // (32, 128)

    // ---- layer 0 ----
    split_plane_kernel<<<2048, 256>>>(x, xh, xl, (size_t)TBm * HH);
    prep_wx_kernel<<<2048, 256>>>(W0, wxh, wxl);
    prep_w_kernel<<<2048, 256>>>(W0, wph, wpl);
    init_state_kernel<<<(BB * HH + 255) / 256, 256>>>(hseqh, hseql, bar);
    gemm_x_bf16<<<ggrid, 256, gsmem>>>(xh, xl, wxh, wxl, zx);
    repack_zx_kernel<<<8192, 256>>>(zx, b0, zxp);
    lstm_persist_kernel<<<PKCTA, 256, psmem>>>(zxp, wph, wpl, hseqh, hseql, hall, bar);

    // ---- layer 1 (gemm A = h sequence planes, slots 1..256) ----
    prep_wx_kernel<<<2048, 256>>>(W1, wxh, wxl);
    prep_w_kernel<<<2048, 256>>>(W1, wph, wpl);
    init_state_kernel<<<(BB * HH + 255) / 256, 256>>>(hseqh, hseql, bar + TT);
    gemm_x_bf16<<<ggrid, 256, gsmem>>>(hseqh + (size_t)BB * HH, hseql + (size_t)BB * HH,
                                       wxh, wxl, zx);
    repack_zx_kernel<<<8192, 256>>>(zx, b1, zxp);
    lstm_persist_kernel<<<PKCTA, 256, psmem>>>(zxp, wph, wpl, hseqh, hseql, out, bar + TT);
}